// round 2
// baseline (speedup 1.0000x reference)
#include <cuda_runtime.h>

#define T_LEN 5000
#define HID   64
#define BATCH 256

// ---- packed f32x2 helpers (FFMA2 only reachable via PTX) ----
__device__ __forceinline__ unsigned long long pack2(float lo, float hi) {
    unsigned long long d;
    asm("mov.b64 %0, {%1, %2};" : "=l"(d) : "f"(lo), "f"(hi));
    return d;
}
__device__ __forceinline__ void unpack2(unsigned long long v, float& lo, float& hi) {
    asm("mov.b64 {%0, %1}, %2;" : "=f"(lo), "=f"(hi) : "l"(v));
}
__device__ __forceinline__ unsigned long long ffma2(unsigned long long a,
                                                    unsigned long long b,
                                                    unsigned long long c) {
    unsigned long long d;
    asm("fma.rn.f32x2 %0, %1, %2, %3;" : "=l"(d) : "l"(a), "l"(b), "l"(c));
    return d;
}

__device__ __forceinline__ float sigmoidf_(float x) {
    return __fdividef(1.0f, 1.0f + __expf(-x));
}
// tanh via 1 - 2/(e^{2x}+1): overflow-safe at both ends (no inf/inf)
__device__ __forceinline__ float tanhf_(float x) {
    float e = __expf(2.0f * x);
    return 1.0f - __fdividef(2.0f, e + 1.0f);
}

__global__ __launch_bounds__(128, 2)
void lstm_fused_kernel(const float* __restrict__ x,
                       const float* __restrict__ W_ih,
                       const float* __restrict__ W_hh,
                       const float* __restrict__ b_ih,
                       const float* __restrict__ b_hh,
                       const float* __restrict__ W_fc,
                       const float* __restrict__ b_fc,
                       float* __restrict__ out)
{
    __shared__ __align__(16) float x_sh[T_LEN];        // whole input row
    __shared__ float2 gates_if[HID];                   // (i, f) per hidden unit
    __shared__ float2 gates_go[HID];                   // (g, o) per hidden unit
    __shared__ __align__(16) float h_dup[2 * HID];     // h duplicated: (h,h) pairs

    const int tid = threadIdx.x;
    const int row = blockIdx.x;

    // ---- stage the full x row (20 KB) into SMEM, coalesced float4 ----
    {
        const float4* xr = reinterpret_cast<const float4*>(x + row * T_LEN);
        float4* xs = reinterpret_cast<float4*>(x_sh);
        for (int i = tid; i < T_LEN / 4; i += 128) xs[i] = xr[i];
    }

    // ---- gate-pair assignment: tid<64 -> (i_u, f_u); tid>=64 -> (g_u, o_u) ----
    const int  u     = tid & 63;
    const bool lower = (tid < 64);
    const int  gA    = lower ? u          : (u + 128);
    const int  gB    = lower ? (u + 64)   : (u + 192);

    // ---- W_hh rows for both gates -> 64 packed b64 registers ----
    unsigned long long w2[HID];
    {
        const float4* ra = reinterpret_cast<const float4*>(W_hh + gA * HID);
        const float4* rb = reinterpret_cast<const float4*>(W_hh + gB * HID);
        #pragma unroll
        for (int i = 0; i < HID / 4; i++) {
            float4 a = ra[i], b = rb[i];
            w2[4 * i + 0] = pack2(a.x, b.x);
            w2[4 * i + 1] = pack2(a.y, b.y);
            w2[4 * i + 2] = pack2(a.z, b.z);
            w2[4 * i + 3] = pack2(a.w, b.w);
        }
    }
    const unsigned long long wih2  = pack2(W_ih[gA], W_ih[gB]);
    const unsigned long long bsum2 = pack2(b_ih[gA] + b_hh[gA],
                                           b_ih[gB] + b_hh[gB]);

    if (tid < HID) { h_dup[2 * tid] = 0.0f; h_dup[2 * tid + 1] = 0.0f; }
    float c = 0.0f;
    __syncthreads();   // covers x_sh staging + h_dup init

    // ================= recurrence: 5000 serial steps =================
    for (int t = 0; t < T_LEN; t++) {
        const float xv = x_sh[t];
        // acc0 carries x-term + biases; acc1 starts at (+0,+0)
        unsigned long long acc0 = ffma2(pack2(xv, xv), wih2, bsum2);
        unsigned long long acc1 = 0ULL;

        #pragma unroll
        for (int k = 0; k < HID; k += 2) {
            // h_dup holds (h[k],h[k],h[k+1],h[k+1]) -> one LDS.128, zero packing ops
            ulonglong2 hv = *reinterpret_cast<const ulonglong2*>(&h_dup[2 * k]);
            acc0 = ffma2(hv.x, w2[k],     acc0);
            acc1 = ffma2(hv.y, w2[k + 1], acc1);
        }

        float a0l, a0h, a1l, a1h;
        unpack2(acc0, a0l, a0h);
        unpack2(acc1, a1l, a1h);
        const float pa = a0l + a1l;   // preact for gate gA
        const float pb = a0h + a1h;   // preact for gate gB

        if (lower) gates_if[u] = make_float2(sigmoidf_(pa), sigmoidf_(pb));
        else       gates_go[u] = make_float2(tanhf_(pa),    sigmoidf_(pb));
        __syncthreads();

        if (tid < HID) {
            float2 iff = gates_if[tid];
            float2 go  = gates_go[tid];
            c = iff.y * c + iff.x * go.x;           // c = f*c + i*g
            float h = go.y * tanhf_(c);             // h = o*tanh(c)
            h_dup[2 * tid]     = h;
            h_dup[2 * tid + 1] = h;
        }
        __syncthreads();
    }

    // ================= FC(64 -> 128) + ReLU epilogue =================
    {
        const float4* wr = reinterpret_cast<const float4*>(W_fc + tid * HID);
        float acc = b_fc[tid];
        #pragma unroll
        for (int i = 0; i < HID / 4; i++) {
            float4 w = wr[i];
            acc += h_dup[2 * (4 * i + 0)] * w.x;
            acc += h_dup[2 * (4 * i + 1)] * w.y;
            acc += h_dup[2 * (4 * i + 2)] * w.z;
            acc += h_dup[2 * (4 * i + 3)] * w.w;
        }
        out[row * 128 + tid] = fmaxf(acc, 0.0f);
    }
}

extern "C" void kernel_launch(void* const* d_in, const int* in_sizes, int n_in,
                              void* d_out, int out_size)
{
    const float* x    = (const float*)d_in[0];
    const float* W_ih = (const float*)d_in[1];
    const float* W_hh = (const float*)d_in[2];
    const float* b_ih = (const float*)d_in[3];
    const float* b_hh = (const float*)d_in[4];
    const float* W_fc = (const float*)d_in[5];
    const float* b_fc = (const float*)d_in[6];

    lstm_fused_kernel<<<BATCH, 128>>>(x, W_ih, W_hh, b_ih, b_hh,
                                      W_fc, b_fc, (float*)d_out);
}